// round 7
// baseline (speedup 1.0000x reference)
#include <cuda_runtime.h>
#include <cstdint>
#include <math.h>

#define B_ 2
#define H_ 16
#define S_ 2048
#define E_ 64
#define NTOK (B_*S_*H_)            // 65536
#define SSTR 68                    // Ss row stride (floats)

// Scratch for projected Q,K,V in [B,H,S,E] layout (48 MB, static device mem)
__device__ float g_q[B_*H_*S_*E_];
__device__ float g_k[B_*H_*S_*E_];
__device__ float g_v[B_*H_*S_*E_];

// ---------------------------------------------------------------------------
// Packed 2xfp32 FMA helpers (sm_100+ PTX: fma.rn.f32x2)
// ---------------------------------------------------------------------------
__device__ __forceinline__ void ffma2(unsigned long long& d,
                                      unsigned long long a,
                                      unsigned long long b) {
    asm("fma.rn.f32x2 %0, %1, %2, %0;" : "+l"(d) : "l"(a), "l"(b));
}
__device__ __forceinline__ void fmul2(unsigned long long& d,
                                      unsigned long long s) {
    asm("mul.rn.f32x2 %0, %0, %1;" : "+l"(d) : "l"(s));
}
__device__ __forceinline__ unsigned long long pack2(float x, float y) {
    unsigned long long r;
    asm("mov.b64 %0, {%1, %2};" : "=l"(r) : "f"(x), "f"(y));
    return r;
}
__device__ __forceinline__ float2 unpack2(unsigned long long v) {
    float lo, hi;
    asm("mov.b64 {%0, %1}, %2;" : "=f"(lo), "=f"(hi) : "l"(v));
    return make_float2(lo, hi);
}

// ---------------------------------------------------------------------------
// Exact JAX threefry2x32, key=(0,42), partitionable counter mode:
// element i -> counter (0,i), output fold x0 ^ x1.
// ---------------------------------------------------------------------------
__device__ __forceinline__ uint32_t threefry_bits_42(uint32_t c1) {
    const uint32_t ks0 = 0u;
    const uint32_t ks1 = 42u;
    const uint32_t ks2 = 0x1BD11BDAu ^ 0u ^ 42u;
    uint32_t x0 = 0u + ks0;
    uint32_t x1 = c1 + ks1;
#define TF_R(r) { x0 += x1; x1 = __funnelshift_l(x1, x1, (r)); x1 ^= x0; }
    TF_R(13) TF_R(15) TF_R(26) TF_R(6)
    x0 += ks1; x1 += ks2 + 1u;
    TF_R(17) TF_R(29) TF_R(16) TF_R(24)
    x0 += ks2; x1 += ks0 + 2u;
    TF_R(13) TF_R(15) TF_R(26) TF_R(6)
    x0 += ks0; x1 += ks1 + 3u;
    TF_R(17) TF_R(29) TF_R(16) TF_R(24)
    x0 += ks1; x1 += ks2 + 4u;
    TF_R(13) TF_R(15) TF_R(26) TF_R(6)
    x0 += ks2; x1 += ks0 + 5u;
#undef TF_R
    return x0 ^ x1;
}

__device__ __forceinline__ float jax_uniform(uint32_t bits) {
    return __uint_as_float((bits >> 9) | 0x3f800000u) - 1.0f;
}

// ---------------------------------------------------------------------------
// Projection: out[b,h,s,e] = sum_d x[b,s,h,d] * W[e,d] + bias[e]
// ---------------------------------------------------------------------------
__global__ __launch_bounds__(256) void proj_kernel(
    const float* __restrict__ x, const float* __restrict__ W,
    const float* __restrict__ bias, int which)
{
    __shared__ float Xs[64][65];
    __shared__ float Ws[64][65];
    __shared__ float bs[64];

    float* out = (which == 0) ? g_q : (which == 1) ? g_k : g_v;

    const int tid = threadIdx.x;
    const int n0  = blockIdx.x * 64;

    #pragma unroll
    for (int it = 0; it < 4; ++it) {
        int elem = tid * 4 + it * 1024;
        int r = elem >> 6, c = elem & 63;
        float4 w4 = *(const float4*)(W + elem);
        Ws[r][c] = w4.x; Ws[r][c+1] = w4.y; Ws[r][c+2] = w4.z; Ws[r][c+3] = w4.w;
        float4 x4 = *(const float4*)(x + (size_t)n0 * 64 + elem);
        Xs[r][c] = x4.x; Xs[r][c+1] = x4.y; Xs[r][c+2] = x4.z; Xs[r][c+3] = x4.w;
    }
    if (tid < 64) bs[tid] = bias[tid];
    __syncthreads();

    const int tx = tid & 15, ty = tid >> 4;
    float acc[4][4] = {};
    #pragma unroll 8
    for (int d = 0; d < 64; ++d) {
        float a[4], b[4];
        #pragma unroll
        for (int i = 0; i < 4; ++i) a[i] = Xs[ty*4+i][d];
        #pragma unroll
        for (int j = 0; j < 4; ++j) b[j] = Ws[tx*4+j][d];
        #pragma unroll
        for (int i = 0; i < 4; ++i)
            #pragma unroll
            for (int j = 0; j < 4; ++j)
                acc[i][j] = fmaf(a[i], b[j], acc[i][j]);
    }

    #pragma unroll
    for (int i = 0; i < 4; ++i) {
        int n   = n0 + ty*4 + i;
        int b_  = n >> 15;
        int rem = n & 32767;
        int s   = rem >> 4;
        int h   = n & 15;
        float* op = out + ((((size_t)b_ * H_ + h) * S_ + s) << 6);
        #pragma unroll
        for (int j = 0; j < 4; ++j) {
            int e = tx*4 + j;
            op[e] = acc[i][j] + bs[e];
        }
    }
}

// ---------------------------------------------------------------------------
// Flash attention: XOR-swizzled smem, f32x2 packed-FMA GEMM phases,
// V stored transposed, ballot-gated exact threefry dropout.
// Smem: Qs[64*64], Ks[64*64], Vt[64*64], Ss[64*SSTR], m/Z/f[64 each]
// ---------------------------------------------------------------------------
#define SMEM_FLOATS (3*64*64 + 64*SSTR + 192)   // 16832 floats = 67328 B

__global__ __launch_bounds__(256, 2) void attn_kernel(
    const float* __restrict__ mask,
    const float* __restrict__ inv_scale,
    float* __restrict__ out)
{
    extern __shared__ float sm[];
    float* Qs = sm;                  // swizzled, stride 64
    float* Ks = sm + 64*64;          // swizzled, stride 64
    float* Vt = sm + 2*64*64;        // transposed + swizzled, stride 64
    float* Ss = sm + 3*64*64;        // stride SSTR
    float* m_s = Ss + 64*SSTR;
    float* Z_s = m_s + 64;
    float* f_s = Z_s + 64;

    const int tid  = threadIdx.x;
    const int s0   = blockIdx.x * 64;
    const int h    = blockIdx.y;
    const int b    = blockIdx.z;
    const float rscale = 1.0f / inv_scale[0];

    const float* Qg = g_q + ((((size_t)b * H_ + h) * S_ + s0) << 6);
    const float* Kg = g_k + ((((size_t)b * H_ + h) * S_) << 6);
    const float* Vg = g_v + ((((size_t)b * H_ + h) * S_) << 6);
    const float* Mg = mask + ((size_t)b * S_ + s0) * S_;

    // load Q tile -> swizzled rows: chunk c4 of row r at c4 ^ (r & 15)
    #pragma unroll
    for (int it = 0; it < 4; ++it) {
        int elem = tid * 4 + it * 1024;
        int r = elem >> 6, c4 = (elem >> 2) & 15;
        *(float4*)&Qs[r*64 + ((c4 ^ (r & 15)) << 2)] = *(const float4*)(Qg + elem);
    }
    if (tid < 64) { m_s[tid] = -INFINITY; Z_s[tid] = 0.0f; }

    const int tx = tid & 15, ty = tid >> 4;
    const int lane = tid & 31, warp = tid >> 5;

    unsigned long long acc2[4][4];   // packed pair-sums over t; cols 4tx+j
    #pragma unroll
    for (int i = 0; i < 4; ++i)
        #pragma unroll
        for (int j = 0; j < 4; ++j) acc2[i][j] = 0ull;

    for (int t0 = 0; t0 < S_; t0 += 64) {
        __syncthreads();
        // K tile (swizzled) + mask tile into Ss
        #pragma unroll
        for (int it = 0; it < 4; ++it) {
            int elem = tid * 4 + it * 1024;
            int r = elem >> 6, c = elem & 63, c4 = c >> 2;
            *(float4*)&Ks[r*64 + ((c4 ^ (r & 15)) << 2)] =
                *(const float4*)(Kg + (((size_t)t0) << 6) + elem);
            *(float4*)&Ss[r*SSTR + c] = *(const float4*)(Mg + (size_t)r * S_ + t0 + c);
        }
        // V tile: transposed-register load -> Vt[col][t], double-XOR swizzle
        #pragma unroll
        for (int it = 0; it < 4; ++it) {
            int unit = tid + it * 256;          // 0..1023
            int col = unit & 63, tc = unit >> 6;
            const float* vp = Vg + (((size_t)(t0 + tc*4)) << 6) + col;
            float4 v4;
            v4.x = vp[0]; v4.y = vp[64]; v4.z = vp[128]; v4.w = vp[192];
            int swz = tc ^ ((col >> 2) & 15) ^ ((col & 3) << 2);
            *(float4*)&Vt[col*64 + (swz << 2)] = v4;
        }
        __syncthreads();

        // S[4ty+i][tx+16j] = (Q K^T)*rscale + mask, packed over e
        {
            unsigned long long sacc2[4][4];
            #pragma unroll
            for (int i = 0; i < 4; ++i)
                #pragma unroll
                for (int j = 0; j < 4; ++j) sacc2[i][j] = 0ull;

            #pragma unroll
            for (int e4 = 0; e4 < 16; ++e4) {
                ulonglong2 qv[4], kv[4];
                #pragma unroll
                for (int i = 0; i < 4; ++i) {
                    int ri = 4*ty + i;
                    qv[i] = *(const ulonglong2*)&Qs[ri*64 + ((e4 ^ (ri & 15)) << 2)];
                }
                #pragma unroll
                for (int j = 0; j < 4; ++j) {
                    int rj = tx + 16*j;        // rj & 15 == tx
                    kv[j] = *(const ulonglong2*)&Ks[rj*64 + ((e4 ^ tx) << 2)];
                }
                #pragma unroll
                for (int i = 0; i < 4; ++i)
                    #pragma unroll
                    for (int j = 0; j < 4; ++j) {
                        ffma2(sacc2[i][j], qv[i].x, kv[j].x);
                        ffma2(sacc2[i][j], qv[i].y, kv[j].y);
                    }
            }
            #pragma unroll
            for (int i = 0; i < 4; ++i)
                #pragma unroll
                for (int j = 0; j < 4; ++j) {
                    float2 p = unpack2(sacc2[i][j]);
                    int idx = (4*ty+i)*SSTR + tx + 16*j;
                    Ss[idx] = fmaf(p.x + p.y, rscale, Ss[idx]);
                }
        }
        __syncthreads();

        // online softmax + ballot-gated exact threefry dropout
        #pragma unroll 1
        for (int k = 0; k < 8; ++k) {
            int r = warp * 8 + k;
            float v0 = Ss[r*SSTR + lane];
            float v1 = Ss[r*SSTR + lane + 32];
            float mx = fmaxf(v0, v1);
            #pragma unroll
            for (int off = 16; off; off >>= 1)
                mx = fmaxf(mx, __shfl_xor_sync(0xffffffffu, mx, off));
            float m_old = m_s[r];
            float m_new = fmaxf(m_old, mx);
            float p0 = __expf(v0 - m_new);
            float p1 = __expf(v1 - m_new);
            float zt = p0 + p1;
            #pragma unroll
            for (int off = 16; off; off >>= 1)
                zt += __shfl_xor_sync(0xffffffffu, zt, off);
            if (lane == 0) {
                float f = __expf(m_old - m_new);
                f_s[r] = f;
                Z_s[r] = Z_s[r] * f + zt;
                m_s[r] = m_new;
            }
            unsigned bal = __ballot_sync(0xffffffffu,
                                         (p0 >= 1e-10f) | (p1 >= 1e-10f));
            if (bal) {
                uint32_t base = (((uint32_t)(b * H_ + h) * (uint32_t)S_
                                  + (uint32_t)(s0 + r)) * (uint32_t)S_)
                              + (uint32_t)t0;
                uint32_t bits0 = threefry_bits_42(base + (uint32_t)lane);
                uint32_t bits1 = threefry_bits_42(base + (uint32_t)lane + 32u);
                Ss[r*SSTR + lane]      = (jax_uniform(bits0) < 0.9f) ? p0 : 0.0f;
                Ss[r*SSTR + lane + 32] = (jax_uniform(bits1) < 0.9f) ? p1 : 0.0f;
            } else {
                Ss[r*SSTR + lane]      = p0;
                Ss[r*SSTR + lane + 32] = p1;
            }
        }
        __syncthreads();

        // PV accumulate, packed over t pairs via V^T
        {
            #pragma unroll
            for (int i = 0; i < 4; ++i) {
                float f = f_s[4*ty+i];
                unsigned long long ff = pack2(f, f);
                #pragma unroll
                for (int j = 0; j < 4; ++j) fmul2(acc2[i][j], ff);
            }
            #pragma unroll
            for (int tc = 0; tc < 16; ++tc) {
                int t = tc << 2;
                ulonglong2 sv[4], vv[4];
                #pragma unroll
                for (int i = 0; i < 4; ++i)
                    sv[i] = *(const ulonglong2*)&Ss[(4*ty+i)*SSTR + t];
                #pragma unroll
                for (int j = 0; j < 4; ++j) {
                    int col = 4*tx + j;
                    int swz = tc ^ tx ^ (j << 2);
                    vv[j] = *(const ulonglong2*)&Vt[col*64 + (swz << 2)];
                }
                #pragma unroll
                for (int i = 0; i < 4; ++i)
                    #pragma unroll
                    for (int j = 0; j < 4; ++j) {
                        ffma2(acc2[i][j], sv[i].x, vv[j].x);
                        ffma2(acc2[i][j], sv[i].y, vv[j].y);
                    }
            }
        }
    }

    // write: out[b,h,s,4tx..4tx+3] = (lo+hi) / (Z * 0.9)
    #pragma unroll
    for (int i = 0; i < 4; ++i) {
        int r = 4*ty + i;
        float invz = 1.0f / (Z_s[r] * 0.9f);
        float* op = out + ((((size_t)b * H_ + h) * S_ + (s0 + r)) << 6);
        float4 o4;
        float2 a0 = unpack2(acc2[i][0]);
        float2 a1 = unpack2(acc2[i][1]);
        float2 a2 = unpack2(acc2[i][2]);
        float2 a3 = unpack2(acc2[i][3]);
        o4.x = (a0.x + a0.y) * invz;
        o4.y = (a1.x + a1.y) * invz;
        o4.z = (a2.x + a2.y) * invz;
        o4.w = (a3.x + a3.y) * invz;
        *(float4*)(op + 4*tx) = o4;
    }
}

// ---------------------------------------------------------------------------
extern "C" void kernel_launch(void* const* d_in, const int* in_sizes, int n_in,
                              void* d_out, int out_size)
{
    const float* query     = (const float*)d_in[0];
    const float* key       = (const float*)d_in[1];
    const float* value     = (const float*)d_in[2];
    const float* attn_mask = (const float*)d_in[3];
    const float* inv_scale = (const float*)d_in[4];
    const float* Wq = (const float*)d_in[5];
    const float* bq = (const float*)d_in[6];
    const float* Wk = (const float*)d_in[7];
    const float* bk = (const float*)d_in[8];
    const float* Wv = (const float*)d_in[9];
    const float* bv = (const float*)d_in[10];
    float* out = (float*)d_out;

    const int nblk = NTOK / 64;   // 1024
    proj_kernel<<<nblk, 256>>>(query, Wq, bq, 0);
    proj_kernel<<<nblk, 256>>>(key,   Wk, bk, 1);
    proj_kernel<<<nblk, 256>>>(value, Wv, bv, 2);

    cudaFuncSetAttribute(attn_kernel,
                         cudaFuncAttributeMaxDynamicSharedMemorySize,
                         SMEM_FLOATS * (int)sizeof(float));
    dim3 grid(S_ / 64, H_, B_);
    attn_kernel<<<grid, 256, SMEM_FLOATS * sizeof(float)>>>(attn_mask, inv_scale, out);
}

// round 9
// speedup vs baseline: 1.8690x; 1.8690x over previous
#include <cuda_runtime.h>
#include <cuda_bf16.h>
#include <cstdint>
#include <math.h>

#define B_ 2
#define H_ 16
#define S_ 2048
#define E_ 64
#define NTOK (B_*S_*H_)
#define BM 128
#define BN 64
#define NT_ (S_/BN)

// bf16 split levels of projected Q,K,V in [B,H,S,E] layout
__device__ __nv_bfloat16 g_q0[B_*H_*S_*E_];
__device__ __nv_bfloat16 g_q1[B_*H_*S_*E_];
__device__ __nv_bfloat16 g_q2[B_*H_*S_*E_];
__device__ __nv_bfloat16 g_k0[B_*H_*S_*E_];
__device__ __nv_bfloat16 g_k1[B_*H_*S_*E_];
__device__ __nv_bfloat16 g_k2[B_*H_*S_*E_];
__device__ __nv_bfloat16 g_v0[B_*H_*S_*E_];
__device__ __nv_bfloat16 g_v1[B_*H_*S_*E_];

// ---------------- helpers ----------------
__device__ __forceinline__ uint32_t smem_u32(const void* p) {
    uint32_t a;
    asm("{ .reg .u64 t; cvta.to.shared.u64 t, %1; cvt.u32.u64 %0, t; }" : "=r"(a) : "l"(p));
    return a;
}
__device__ __forceinline__ void ldsm_x4(uint32_t& r0, uint32_t& r1, uint32_t& r2,
                                        uint32_t& r3, uint32_t a) {
    asm volatile("ldmatrix.sync.aligned.m8n8.x4.shared.b16 {%0,%1,%2,%3}, [%4];"
                 : "=r"(r0), "=r"(r1), "=r"(r2), "=r"(r3) : "r"(a));
}
__device__ __forceinline__ void ldsm_x2(uint32_t& r0, uint32_t& r1, uint32_t a) {
    asm volatile("ldmatrix.sync.aligned.m8n8.x2.shared.b16 {%0,%1}, [%2];"
                 : "=r"(r0), "=r"(r1) : "r"(a));
}
__device__ __forceinline__ void ldsm_x2t(uint32_t& r0, uint32_t& r1, uint32_t a) {
    asm volatile("ldmatrix.sync.aligned.m8n8.x2.trans.shared.b16 {%0,%1}, [%2];"
                 : "=r"(r0), "=r"(r1) : "r"(a));
}
__device__ __forceinline__ void mma_bf16(float* c, const uint32_t* a,
                                         uint32_t b0, uint32_t b1) {
    asm volatile("mma.sync.aligned.m16n8k16.row.col.f32.bf16.bf16.f32 "
                 "{%0,%1,%2,%3}, {%4,%5,%6,%7}, {%8,%9}, {%0,%1,%2,%3};"
                 : "+f"(c[0]), "+f"(c[1]), "+f"(c[2]), "+f"(c[3])
                 : "r"(a[0]), "r"(a[1]), "r"(a[2]), "r"(a[3]), "r"(b0), "r"(b1));
}
__device__ __forceinline__ uint32_t packbf(float x, float y) {
    __nv_bfloat162 t = __floats2bfloat162_rn(x, y);
    return *(uint32_t*)&t;
}

// ---------------- exact JAX threefry, key=(0,42), partitionable ----------------
__device__ __forceinline__ uint32_t threefry_bits_42(uint32_t c1) {
    const uint32_t ks1 = 42u, ks2 = 0x1BD11BDAu ^ 42u;
    uint32_t x0 = 0u, x1 = c1 + ks1;
#define TF_R(r) { x0 += x1; x1 = __funnelshift_l(x1, x1, (r)); x1 ^= x0; }
    TF_R(13) TF_R(15) TF_R(26) TF_R(6)
    x0 += ks1; x1 += ks2 + 1u;
    TF_R(17) TF_R(29) TF_R(16) TF_R(24)
    x0 += ks2; x1 += 2u;
    TF_R(13) TF_R(15) TF_R(26) TF_R(6)
    x1 += ks1 + 3u;
    TF_R(17) TF_R(29) TF_R(16) TF_R(24)
    x0 += ks1; x1 += ks2 + 4u;
    TF_R(13) TF_R(15) TF_R(26) TF_R(6)
    x0 += ks2; x1 += 5u;
#undef TF_R
    return x0 ^ x1;
}
__device__ __forceinline__ float jax_uniform(uint32_t bits) {
    return __uint_as_float((bits >> 9) | 0x3f800000u) - 1.0f;
}

// ---------------- projection with bf16 split outputs ----------------
__global__ __launch_bounds__(256) void proj_kernel(
    const float* __restrict__ x, const float* __restrict__ W,
    const float* __restrict__ bias, int which)
{
    __shared__ float Xs[64][65];
    __shared__ float Ws[64][65];
    __shared__ float bs[64];
    __nv_bfloat16* o0 = (which == 0) ? g_q0 : (which == 1) ? g_k0 : g_v0;
    __nv_bfloat16* o1 = (which == 0) ? g_q1 : (which == 1) ? g_k1 : g_v1;
    __nv_bfloat16* o2 = (which == 0) ? g_q2 : g_k2;  // unused for v
    const int tid = threadIdx.x;
    const int n0  = blockIdx.x * 64;
    #pragma unroll
    for (int it = 0; it < 4; ++it) {
        int elem = tid * 4 + it * 1024;
        int r = elem >> 6, c = elem & 63;
        float4 w4 = *(const float4*)(W + elem);
        Ws[r][c] = w4.x; Ws[r][c+1] = w4.y; Ws[r][c+2] = w4.z; Ws[r][c+3] = w4.w;
        float4 x4 = *(const float4*)(x + (size_t)n0 * 64 + elem);
        Xs[r][c] = x4.x; Xs[r][c+1] = x4.y; Xs[r][c+2] = x4.z; Xs[r][c+3] = x4.w;
    }
    if (tid < 64) bs[tid] = bias[tid];
    __syncthreads();
    const int tx = tid & 15, ty = tid >> 4;
    float acc[4][4] = {};
    #pragma unroll 8
    for (int d = 0; d < 64; ++d) {
        float a[4], b[4];
        #pragma unroll
        for (int i = 0; i < 4; ++i) a[i] = Xs[ty*4+i][d];
        #pragma unroll
        for (int j = 0; j < 4; ++j) b[j] = Ws[tx*4+j][d];
        #pragma unroll
        for (int i = 0; i < 4; ++i)
            #pragma unroll
            for (int j = 0; j < 4; ++j)
                acc[i][j] = fmaf(a[i], b[j], acc[i][j]);
    }
    #pragma unroll
    for (int i = 0; i < 4; ++i) {
        int n = n0 + ty*4 + i;
        int b_ = n >> 15, rem = n & 32767, s = rem >> 4, h = n & 15;
        size_t off = ((((size_t)b_ * H_ + h) * S_ + s) << 6);
        #pragma unroll
        for (int j = 0; j < 4; ++j) {
            int e = tx*4 + j;
            float v = acc[i][j] + bs[e];
            __nv_bfloat16 h0 = __float2bfloat16(v);
            float r0 = v - __bfloat162float(h0);
            __nv_bfloat16 h1 = __float2bfloat16(r0);
            o0[off + e] = h0;
            o1[off + e] = h1;
            if (which != 2) {
                float r1 = r0 - __bfloat162float(h1);
                o2[off + e] = __float2bfloat16(r1);
            }
        }
    }
}

// ---------------- mma.sync flash attention ----------------
// smem byte offsets: rows of 64 bf16 = 128 B, XOR-swizzled in 16B chunks
#define SQ0 0
#define SQ1 16384
#define SQ2 32768
#define SK0 49152
#define SK1 57344
#define SK2 65536
#define SV0 73728
#define SV1 81920
#define SMEM_TOT 90112
__device__ __forceinline__ int swb(int r, int c8) {
    return r * 128 + ((c8 ^ (r & 7)) << 4);
}

__global__ __launch_bounds__(256, 2) void attn_kernel(
    const float* __restrict__ mask,
    const float* __restrict__ inv_scale,
    float* __restrict__ out)
{
    extern __shared__ char smem[];
    const uint32_t sb = smem_u32(smem);
    const int tid = threadIdx.x, warp = tid >> 5, lane = tid & 31;
    const int s0 = blockIdx.x * BM, h = blockIdx.y, b = blockIdx.z;
    const int bh = b * H_ + h;
    const float rscale = 1.0f / inv_scale[0];

    // stage Q (3 levels) rows s0..s0+127
    const size_t qrow = (size_t)bh * S_ + s0;
    for (int c = tid; c < 128 * 8; c += 256) {
        int r = c >> 3, c8 = c & 7;
        size_t ge = ((qrow + r) << 6) + (c8 << 3);
        int so = swb(r, c8);
        *(uint4*)(smem + SQ0 + so) = *(const uint4*)(g_q0 + ge);
        *(uint4*)(smem + SQ1 + so) = *(const uint4*)(g_q1 + ge);
        *(uint4*)(smem + SQ2 + so) = *(const uint4*)(g_q2 + ge);
    }

    const int qr = lane >> 2;          // 0..7
    const int qc = (lane & 3) << 1;    // 0,2,4,6
    const int rg0 = s0 + warp * 16 + qr;
    const int rg1 = rg0 + 8;
    const float* mrow0 = mask + ((size_t)b * S_ + rg0) * S_;
    const float* mrow1 = mask + ((size_t)b * S_ + rg1) * S_;
    const uint32_t cb0 = ((uint32_t)bh * S_ + (uint32_t)rg0) * S_;
    const uint32_t cb1 = ((uint32_t)bh * S_ + (uint32_t)rg1) * S_;
    const size_t kplane = (size_t)bh * S_;

    float m0 = -INFINITY, m1 = -INFINITY, Z0 = 0.0f, Z1 = 0.0f;
    float Oa[8][4];
    #pragma unroll
    for (int d = 0; d < 8; ++d)
        #pragma unroll
        for (int j = 0; j < 4; ++j) Oa[d][j] = 0.0f;

    for (int it = 0; it < NT_; ++it) {
        const int t0 = it * BN;
        __syncthreads();
        // stage K (3 levels) + V (2 levels), 64 rows each
        for (int c = tid; c < 64 * 8; c += 256) {
            int r = c >> 3, c8 = c & 7;
            size_t ge = ((kplane + t0 + r) << 6) + (c8 << 3);
            int so = swb(r, c8);
            *(uint4*)(smem + SK0 + so) = *(const uint4*)(g_k0 + ge);
            *(uint4*)(smem + SK1 + so) = *(const uint4*)(g_k1 + ge);
            *(uint4*)(smem + SK2 + so) = *(const uint4*)(g_k2 + ge);
            *(uint4*)(smem + SV0 + so) = *(const uint4*)(g_v0 + ge);
            *(uint4*)(smem + SV1 + so) = *(const uint4*)(g_v1 + ge);
        }
        __syncthreads();

        // ---- QK^T: 6-term bf16 split ----
        float sacc[8][4];
        #pragma unroll
        for (int nt = 0; nt < 8; ++nt)
            #pragma unroll
            for (int j = 0; j < 4; ++j) sacc[nt][j] = 0.0f;

        #pragma unroll
        for (int ks = 0; ks < 4; ++ks) {
            const int lr  = warp * 16 + (lane & 7) + ((lane >> 3) & 1) * 8;
            const int lc8 = 2 * ks + (lane >> 4);
            const uint32_t aoff = (uint32_t)swb(lr, lc8);
            uint32_t aH[4], aM[4], aL[4];
            ldsm_x4(aH[0], aH[1], aH[2], aH[3], sb + SQ0 + aoff);
            ldsm_x4(aM[0], aM[1], aM[2], aM[3], sb + SQ1 + aoff);
            ldsm_x4(aL[0], aL[1], aL[2], aL[3], sb + SQ2 + aoff);
            #pragma unroll
            for (int nt = 0; nt < 8; ++nt) {
                const int br  = nt * 8 + (lane & 7);
                const int bc8 = 2 * ks + ((lane >> 3) & 1);
                const uint32_t boff = (uint32_t)swb(br, bc8);
                uint32_t bH0, bH1, bM0, bM1, bL0, bL1;
                ldsm_x2(bH0, bH1, sb + SK0 + boff);
                ldsm_x2(bM0, bM1, sb + SK1 + boff);
                ldsm_x2(bL0, bL1, sb + SK2 + boff);
                mma_bf16(sacc[nt], aH, bH0, bH1);   // hh
                mma_bf16(sacc[nt], aH, bM0, bM1);   // hm
                mma_bf16(sacc[nt], aM, bH0, bH1);   // mh
                mma_bf16(sacc[nt], aH, bL0, bL1);   // hl
                mma_bf16(sacc[nt], aL, bH0, bH1);   // lh
                mma_bf16(sacc[nt], aM, bM0, bM1);   // mm
            }
        }

        // ---- scale + mask, tile row max ----
        float tm0 = -INFINITY, tm1 = -INFINITY;
        #pragma unroll
        for (int nt = 0; nt < 8; ++nt) {
            float2 mk0 = *(const float2*)(mrow0 + t0 + nt * 8 + qc);
            float2 mk1 = *(const float2*)(mrow1 + t0 + nt * 8 + qc);
            sacc[nt][0] = fmaf(sacc[nt][0], rscale, mk0.x);
            sacc[nt][1] = fmaf(sacc[nt][1], rscale, mk0.y);
            sacc[nt][2] = fmaf(sacc[nt][2], rscale, mk1.x);
            sacc[nt][3] = fmaf(sacc[nt][3], rscale, mk1.y);
            tm0 = fmaxf(tm0, fmaxf(sacc[nt][0], sacc[nt][1]));
            tm1 = fmaxf(tm1, fmaxf(sacc[nt][2], sacc[nt][3]));
        }
        tm0 = fmaxf(tm0, __shfl_xor_sync(0xffffffffu, tm0, 1));
        tm0 = fmaxf(tm0, __shfl_xor_sync(0xffffffffu, tm0, 2));
        tm1 = fmaxf(tm1, __shfl_xor_sync(0xffffffffu, tm1, 1));
        tm1 = fmaxf(tm1, __shfl_xor_sync(0xffffffffu, tm1, 2));
        const float mn0 = fmaxf(m0, tm0), mn1 = fmaxf(m1, tm1);
        const float f0 = __expf(m0 - mn0), f1 = __expf(m1 - mn1);
        m0 = mn0; m1 = mn1;

        // ---- exp + dropout ----
        float zs0 = 0.0f, zs1 = 0.0f;
        #pragma unroll
        for (int nt = 0; nt < 8; ++nt) {
            const uint32_t colb = (uint32_t)(t0 + nt * 8 + qc);
            #pragma unroll
            for (int j = 0; j < 2; ++j) {
                float p = __expf(sacc[nt][j] - mn0);
                zs0 += p;
                if (p >= 1e-10f) {
                    uint32_t bits = threefry_bits_42(cb0 + colb + (uint32_t)j);
                    if (!(jax_uniform(bits) < 0.9f)) p = 0.0f;
                }
                sacc[nt][j] = p;
            }
            #pragma unroll
            for (int j = 0; j < 2; ++j) {
                float p = __expf(sacc[nt][2 + j] - mn1);
                zs1 += p;
                if (p >= 1e-10f) {
                    uint32_t bits = threefry_bits_42(cb1 + colb + (uint32_t)j);
                    if (!(jax_uniform(bits) < 0.9f)) p = 0.0f;
                }
                sacc[nt][2 + j] = p;
            }
        }
        zs0 += __shfl_xor_sync(0xffffffffu, zs0, 1);
        zs0 += __shfl_xor_sync(0xffffffffu, zs0, 2);
        zs1 += __shfl_xor_sync(0xffffffffu, zs1, 1);
        zs1 += __shfl_xor_sync(0xffffffffu, zs1, 2);
        Z0 = Z0 * f0 + zs0;
        Z1 = Z1 * f1 + zs1;

        // ---- rescale O ----
        #pragma unroll
        for (int d = 0; d < 8; ++d) {
            Oa[d][0] *= f0; Oa[d][1] *= f0;
            Oa[d][2] *= f1; Oa[d][3] *= f1;
        }

        // ---- PV: P from regs (2-level), V from smem ----
        #pragma unroll
        for (int ks = 0; ks < 4; ++ks) {
            uint32_t ah[4], al[4];
            #pragma unroll
            for (int half = 0; half < 2; ++half) {     // tiles 2ks, 2ks+1
                const int nt = 2 * ks + half;
                float pA = sacc[nt][0], pB = sacc[nt][1];
                float pC = sacc[nt][2], pD = sacc[nt][3];
                __nv_bfloat162 hAB = __floats2bfloat162_rn(pA, pB);
                __nv_bfloat162 hCD = __floats2bfloat162_rn(pC, pD);
                ah[half * 2 + 0] = ((uint32_t*)&hAB)[0];
                ah[half * 2 + 1] = ((uint32_t*)&hCD)[0];
                float lA = pA - __bfloat162float(__low2bfloat16(hAB));
                float lB = pB - __bfloat162float(__high2bfloat16(hAB));
                float lC = pC - __bfloat162float(__low2bfloat16(hCD));
                float lD = pD - __bfloat162float(__high2bfloat16(hCD));
                al[half * 2 + 0] = packbf(lA, lB);
                al[half * 2 + 1] = packbf(lC, lD);
            }
            // reorder: a-frag = {tile2ks rowsR0, tile2ks rowsR1, tile2ks+1 R0, tile2ks+1 R1}
            uint32_t AH[4] = { ah[0], ah[1], ah[2], ah[3] };
            uint32_t AL[4] = { al[0], al[1], al[2], al[3] };
            #pragma unroll
            for (int dt = 0; dt < 8; ++dt) {
                const int vr = 16 * ks + (lane & 15);
                const uint32_t voff = (uint32_t)swb(vr, dt);
                uint32_t v00, v01, v10, v11;
                ldsm_x2t(v00, v01, sb + SV0 + voff);
                ldsm_x2t(v10, v11, sb + SV1 + voff);
                mma_bf16(Oa[dt], AH, v00, v01);   // ph*vh
                mma_bf16(Oa[dt], AH, v10, v11);   // ph*vl
                mma_bf16(Oa[dt], AL, v00, v01);   // pl*vh
            }
        }
    }

    // ---- epilogue ----
    const float iz0 = 1.0f / (Z0 * 0.9f);
    const float iz1 = 1.0f / (Z1 * 0.9f);
    float* orow0 = out + (((size_t)bh * S_ + rg0) << 6);
    float* orow1 = out + (((size_t)bh * S_ + rg1) << 6);
    #pragma unroll
    for (int dt = 0; dt < 8; ++dt) {
        float2 w0 = make_float2(Oa[dt][0] * iz0, Oa[dt][1] * iz0);
        float2 w1 = make_float2(Oa[dt][2] * iz1, Oa[dt][3] * iz1);
        *(float2*)(orow0 + dt * 8 + qc) = w0;
        *(float2*)(orow1 + dt * 8 + qc) = w1;
    }
}

// ---------------------------------------------------------------------------
extern "C" void kernel_launch(void* const* d_in, const int* in_sizes, int n_in,
                              void* d_out, int out_size)
{
    const float* query     = (const float*)d_in[0];
    const float* key       = (const float*)d_in[1];
    const float* value     = (const float*)d_in[2];
    const float* attn_mask = (const float*)d_in[3];
    const float* inv_scale = (const float*)d_in[4];
    const float* Wq = (const float*)d_in[5];
    const float* bq = (const float*)d_in[6];
    const float* Wk = (const float*)d_in[7];
    const float* bk = (const float*)d_in[8];
    const float* Wv = (const float*)d_in[9];
    const float* bv = (const float*)d_in[10];
    float* out = (float*)d_out;

    const int nblk = NTOK / 64;
    proj_kernel<<<nblk, 256>>>(query, Wq, bq, 0);
    proj_kernel<<<nblk, 256>>>(key,   Wk, bk, 1);
    proj_kernel<<<nblk, 256>>>(value, Wv, bv, 2);

    cudaFuncSetAttribute(attn_kernel,
                         cudaFuncAttributeMaxDynamicSharedMemorySize, SMEM_TOT);
    dim3 grid(S_ / BM, H_, B_);
    attn_kernel<<<grid, 256, SMEM_TOT>>>(attn_mask, inv_scale, out);
}

// round 10
// speedup vs baseline: 2.3059x; 1.2337x over previous
#include <cuda_runtime.h>
#include <cuda_fp16.h>
#include <cstdint>
#include <math.h>

#define B_ 2
#define H_ 16
#define S_ 2048
#define E_ 64
#define NTOK (B_*S_*H_)
#define BM 128
#define BN 64
#define NT_ (S_/BN)

// fp16 split levels of projected Q,K,V in [B,H,S,E] layout
__device__ __half g_q0[B_*H_*S_*E_];
__device__ __half g_q1[B_*H_*S_*E_];
__device__ __half g_k0[B_*H_*S_*E_];
__device__ __half g_k1[B_*H_*S_*E_];
__device__ __half g_v0[B_*H_*S_*E_];
__device__ __half g_v1[B_*H_*S_*E_];

// ---------------- helpers ----------------
__device__ __forceinline__ uint32_t smem_u32(const void* p) {
    uint32_t a;
    asm("{ .reg .u64 t; cvta.to.shared.u64 t, %1; cvt.u32.u64 %0, t; }" : "=r"(a) : "l"(p));
    return a;
}
__device__ __forceinline__ void ldsm_x4(uint32_t& r0, uint32_t& r1, uint32_t& r2,
                                        uint32_t& r3, uint32_t a) {
    asm volatile("ldmatrix.sync.aligned.m8n8.x4.shared.b16 {%0,%1,%2,%3}, [%4];"
                 : "=r"(r0), "=r"(r1), "=r"(r2), "=r"(r3) : "r"(a));
}
__device__ __forceinline__ void ldsm_x4t(uint32_t& r0, uint32_t& r1, uint32_t& r2,
                                         uint32_t& r3, uint32_t a) {
    asm volatile("ldmatrix.sync.aligned.m8n8.x4.trans.shared.b16 {%0,%1,%2,%3}, [%4];"
                 : "=r"(r0), "=r"(r1), "=r"(r2), "=r"(r3) : "r"(a));
}
__device__ __forceinline__ void mma_f16(float* c, const uint32_t* a,
                                        uint32_t b0, uint32_t b1) {
    asm volatile("mma.sync.aligned.m16n8k16.row.col.f32.f16.f16.f32 "
                 "{%0,%1,%2,%3}, {%4,%5,%6,%7}, {%8,%9}, {%0,%1,%2,%3};"
                 : "+f"(c[0]), "+f"(c[1]), "+f"(c[2]), "+f"(c[3])
                 : "r"(a[0]), "r"(a[1]), "r"(a[2]), "r"(a[3]), "r"(b0), "r"(b1));
}
__device__ __forceinline__ uint32_t packh2(float x, float y) {
    __half2 t = __floats2half2_rn(x, y);
    return *(uint32_t*)&t;
}

// ---------------- exact JAX threefry, key=(0,42), partitionable ----------------
__device__ __forceinline__ uint32_t threefry_bits_42(uint32_t c1) {
    const uint32_t ks1 = 42u, ks2 = 0x1BD11BDAu ^ 42u;
    uint32_t x0 = 0u, x1 = c1 + ks1;
#define TF_R(r) { x0 += x1; x1 = __funnelshift_l(x1, x1, (r)); x1 ^= x0; }
    TF_R(13) TF_R(15) TF_R(26) TF_R(6)
    x0 += ks1; x1 += ks2 + 1u;
    TF_R(17) TF_R(29) TF_R(16) TF_R(24)
    x0 += ks2; x1 += 2u;
    TF_R(13) TF_R(15) TF_R(26) TF_R(6)
    x1 += ks1 + 3u;
    TF_R(17) TF_R(29) TF_R(16) TF_R(24)
    x0 += ks1; x1 += ks2 + 4u;
    TF_R(13) TF_R(15) TF_R(26) TF_R(6)
    x0 += ks2; x1 += 5u;
#undef TF_R
    return x0 ^ x1;
}
__device__ __forceinline__ float jax_uniform(uint32_t bits) {
    return __uint_as_float((bits >> 9) | 0x3f800000u) - 1.0f;
}

// ---------------- projection with fp16 2-level split outputs ----------------
__global__ __launch_bounds__(256) void proj_kernel(
    const float* __restrict__ x, const float* __restrict__ W,
    const float* __restrict__ bias, int which)
{
    __shared__ float Xs[64][65];
    __shared__ float Ws[64][65];
    __shared__ float bs[64];
    __half* o0 = (which == 0) ? g_q0 : (which == 1) ? g_k0 : g_v0;
    __half* o1 = (which == 0) ? g_q1 : (which == 1) ? g_k1 : g_v1;
    const int tid = threadIdx.x;
    const int n0  = blockIdx.x * 64;
    #pragma unroll
    for (int it = 0; it < 4; ++it) {
        int elem = tid * 4 + it * 1024;
        int r = elem >> 6, c = elem & 63;
        float4 w4 = *(const float4*)(W + elem);
        Ws[r][c] = w4.x; Ws[r][c+1] = w4.y; Ws[r][c+2] = w4.z; Ws[r][c+3] = w4.w;
        float4 x4 = *(const float4*)(x + (size_t)n0 * 64 + elem);
        Xs[r][c] = x4.x; Xs[r][c+1] = x4.y; Xs[r][c+2] = x4.z; Xs[r][c+3] = x4.w;
    }
    if (tid < 64) bs[tid] = bias[tid];
    __syncthreads();
    const int tx = tid & 15, ty = tid >> 4;
    float acc[4][4] = {};
    #pragma unroll 8
    for (int d = 0; d < 64; ++d) {
        float a[4], b[4];
        #pragma unroll
        for (int i = 0; i < 4; ++i) a[i] = Xs[ty*4+i][d];
        #pragma unroll
        for (int j = 0; j < 4; ++j) b[j] = Ws[tx*4+j][d];
        #pragma unroll
        for (int i = 0; i < 4; ++i)
            #pragma unroll
            for (int j = 0; j < 4; ++j)
                acc[i][j] = fmaf(a[i], b[j], acc[i][j]);
    }
    #pragma unroll
    for (int i = 0; i < 4; ++i) {
        int n = n0 + ty*4 + i;
        int b_ = n >> 15, rem = n & 32767, s = rem >> 4, h = n & 15;
        size_t off = ((((size_t)b_ * H_ + h) * S_ + s) << 6);
        #pragma unroll
        for (int j = 0; j < 4; ++j) {
            int e = tx*4 + j;
            float v = acc[i][j] + bs[e];
            __half h0 = __float2half_rn(v);
            o0[off + e] = h0;
            o1[off + e] = __float2half_rn(v - __half2float(h0));
        }
    }
}

// ---------------- mma.sync fp16 flash attention ----------------
// smem: rows of 64 fp16 = 128 B, XOR-swizzled 16B chunks; mask stride-72 f32
#define SQ0 0
#define SQ1 16384
#define SK0 32768
#define SK1 40960
#define SV0 49152
#define SV1 57344
#define SMK 65536
#define SMEM_TOT (65536 + 128*72*4)   // 102400
#define MSTR 72
__device__ __forceinline__ int swb(int r, int c8) {
    return r * 128 + ((c8 ^ (r & 7)) << 4);
}

__global__ __launch_bounds__(256, 2) void attn_kernel(
    const float* __restrict__ mask,
    const float* __restrict__ inv_scale,
    float* __restrict__ out)
{
    extern __shared__ char smem[];
    const uint32_t sb = smem_u32(smem);
    float* Ms = (float*)(smem + SMK);
    const int tid = threadIdx.x, warp = tid >> 5, lane = tid & 31;
    const int s0 = blockIdx.x * BM, h = blockIdx.y, b = blockIdx.z;
    const int bh = b * H_ + h;
    const float rscale = 1.0f / inv_scale[0];

    // stage Q (2 levels)
    const size_t qrow = (size_t)bh * S_ + s0;
    for (int c = tid; c < 128 * 8; c += 256) {
        int r = c >> 3, c8 = c & 7;
        size_t ge = ((qrow + r) << 6) + (c8 << 3);
        int so = swb(r, c8);
        *(uint4*)(smem + SQ0 + so) = *(const uint4*)(g_q0 + ge);
        *(uint4*)(smem + SQ1 + so) = *(const uint4*)(g_q1 + ge);
    }

    const int qr = lane >> 2;
    const int qc = (lane & 3) << 1;
    const int rg0 = s0 + warp * 16 + qr;
    const int rg1 = rg0 + 8;
    const int mr0 = warp * 16 + qr, mr1 = mr0 + 8;
    const uint32_t cb0 = ((uint32_t)bh * S_ + (uint32_t)rg0) * S_;
    const uint32_t cb1 = ((uint32_t)bh * S_ + (uint32_t)rg1) * S_;
    const size_t kplane = (size_t)bh * S_;
    const float* mbase = mask + (size_t)b * S_ * S_;

    float m0 = -INFINITY, m1 = -INFINITY, Z0 = 0.0f, Z1 = 0.0f;
    float Oa[8][4];
    #pragma unroll
    for (int d = 0; d < 8; ++d)
        #pragma unroll
        for (int j = 0; j < 4; ++j) Oa[d][j] = 0.0f;

    for (int it = 0; it < NT_; ++it) {
        const int t0 = it * BN;
        __syncthreads();
        // stage K,V (2 levels each) + mask tile
        for (int c = tid; c < 64 * 8; c += 256) {
            int r = c >> 3, c8 = c & 7;
            size_t ge = ((kplane + t0 + r) << 6) + (c8 << 3);
            int so = swb(r, c8);
            *(uint4*)(smem + SK0 + so) = *(const uint4*)(g_k0 + ge);
            *(uint4*)(smem + SK1 + so) = *(const uint4*)(g_k1 + ge);
            *(uint4*)(smem + SV0 + so) = *(const uint4*)(g_v0 + ge);
            *(uint4*)(smem + SV1 + so) = *(const uint4*)(g_v1 + ge);
        }
        for (int c = tid; c < 128 * 16; c += 256) {
            int r = c >> 4, c4 = (c & 15) << 2;
            *(float4*)(Ms + r * MSTR + c4) =
                *(const float4*)(mbase + (size_t)(s0 + r) * S_ + t0 + c4);
        }
        __syncthreads();

        // ---- QK^T: fp16 2-level, 3 terms (hh, hm, mh) ----
        float sacc[8][4];
        #pragma unroll
        for (int nt = 0; nt < 8; ++nt)
            #pragma unroll
            for (int j = 0; j < 4; ++j) sacc[nt][j] = 0.0f;

        #pragma unroll
        for (int ks = 0; ks < 4; ++ks) {
            const int lr  = warp * 16 + (lane & 7) + ((lane >> 3) & 1) * 8;
            const int lc8 = 2 * ks + (lane >> 4);
            const uint32_t aoff = (uint32_t)swb(lr, lc8);
            uint32_t aH[4], aM[4];
            ldsm_x4(aH[0], aH[1], aH[2], aH[3], sb + SQ0 + aoff);
            ldsm_x4(aM[0], aM[1], aM[2], aM[3], sb + SQ1 + aoff);
            const int br  = (lane & 7) + ((lane >> 4) << 3);
            const int bc8 = 2 * ks + ((lane >> 3) & 1);
            #pragma unroll
            for (int np = 0; np < 4; ++np) {
                const uint32_t boff = (uint32_t)swb(np * 16 + br, bc8);
                uint32_t bh4[4], bm4[4];
                ldsm_x4(bh4[0], bh4[1], bh4[2], bh4[3], sb + SK0 + boff);
                ldsm_x4(bm4[0], bm4[1], bm4[2], bm4[3], sb + SK1 + boff);
                mma_f16(sacc[2*np],   aH, bh4[0], bh4[1]);
                mma_f16(sacc[2*np],   aH, bm4[0], bm4[1]);
                mma_f16(sacc[2*np],   aM, bh4[0], bh4[1]);
                mma_f16(sacc[2*np+1], aH, bh4[2], bh4[3]);
                mma_f16(sacc[2*np+1], aH, bm4[2], bm4[3]);
                mma_f16(sacc[2*np+1], aM, bh4[2], bh4[3]);
            }
        }

        // ---- scale + mask (from smem), tile row max ----
        float tm0 = -INFINITY, tm1 = -INFINITY;
        #pragma unroll
        for (int nt = 0; nt < 8; ++nt) {
            float2 mk0 = *(const float2*)(Ms + mr0 * MSTR + nt * 8 + qc);
            float2 mk1 = *(const float2*)(Ms + mr1 * MSTR + nt * 8 + qc);
            sacc[nt][0] = fmaf(sacc[nt][0], rscale, mk0.x);
            sacc[nt][1] = fmaf(sacc[nt][1], rscale, mk0.y);
            sacc[nt][2] = fmaf(sacc[nt][2], rscale, mk1.x);
            sacc[nt][3] = fmaf(sacc[nt][3], rscale, mk1.y);
            tm0 = fmaxf(tm0, fmaxf(sacc[nt][0], sacc[nt][1]));
            tm1 = fmaxf(tm1, fmaxf(sacc[nt][2], sacc[nt][3]));
        }
        tm0 = fmaxf(tm0, __shfl_xor_sync(0xffffffffu, tm0, 1));
        tm0 = fmaxf(tm0, __shfl_xor_sync(0xffffffffu, tm0, 2));
        tm1 = fmaxf(tm1, __shfl_xor_sync(0xffffffffu, tm1, 1));
        tm1 = fmaxf(tm1, __shfl_xor_sync(0xffffffffu, tm1, 2));
        const float mn0 = fmaxf(m0, tm0), mn1 = fmaxf(m1, tm1);
        const float f0 = __expf(m0 - mn0), f1 = __expf(m1 - mn1);
        m0 = mn0; m1 = mn1;

        // ---- exp + gated exact dropout ----
        float zs0 = 0.0f, zs1 = 0.0f;
        #pragma unroll
        for (int nt = 0; nt < 8; ++nt) {
            const uint32_t colb = (uint32_t)(t0 + nt * 8 + qc);
            #pragma unroll
            for (int j = 0; j < 2; ++j) {
                float p = __expf(sacc[nt][j] - mn0);
                zs0 += p;
                if (p >= 1e-10f) {
                    uint32_t bits = threefry_bits_42(cb0 + colb + (uint32_t)j);
                    if (!(jax_uniform(bits) < 0.9f)) p = 0.0f;
                }
                sacc[nt][j] = p;
            }
            #pragma unroll
            for (int j = 0; j < 2; ++j) {
                float p = __expf(sacc[nt][2 + j] - mn1);
                zs1 += p;
                if (p >= 1e-10f) {
                    uint32_t bits = threefry_bits_42(cb1 + colb + (uint32_t)j);
                    if (!(jax_uniform(bits) < 0.9f)) p = 0.0f;
                }
                sacc[nt][2 + j] = p;
            }
        }
        zs0 += __shfl_xor_sync(0xffffffffu, zs0, 1);
        zs0 += __shfl_xor_sync(0xffffffffu, zs0, 2);
        zs1 += __shfl_xor_sync(0xffffffffu, zs1, 1);
        zs1 += __shfl_xor_sync(0xffffffffu, zs1, 2);
        Z0 = Z0 * f0 + zs0;
        Z1 = Z1 * f1 + zs1;

        // ---- rescale O ----
        #pragma unroll
        for (int d = 0; d < 8; ++d) {
            Oa[d][0] *= f0; Oa[d][1] *= f0;
            Oa[d][2] *= f1; Oa[d][3] *= f1;
        }

        // ---- PV: fp16 2-level P from regs, V x4t from smem ----
        #pragma unroll
        for (int ks = 0; ks < 4; ++ks) {
            uint32_t AH[4], AL[4];
            #pragma unroll
            for (int half = 0; half < 2; ++half) {
                const int nt = 2 * ks + half;
                float pA = sacc[nt][0], pB = sacc[nt][1];
                float pC = sacc[nt][2], pD = sacc[nt][3];
                __half2 hAB = __floats2half2_rn(pA, pB);
                __half2 hCD = __floats2half2_rn(pC, pD);
                AH[half * 2 + 0] = *(uint32_t*)&hAB;
                AH[half * 2 + 1] = *(uint32_t*)&hCD;
                float lA = pA - __half2float(__low2half(hAB));
                float lB = pB - __half2float(__high2half(hAB));
                float lC = pC - __half2float(__low2half(hCD));
                float lD = pD - __half2float(__high2half(hCD));
                AL[half * 2 + 0] = packh2(lA, lB);
                AL[half * 2 + 1] = packh2(lC, lD);
            }
            const int vr = 16 * ks + (lane & 15);
            #pragma unroll
            for (int dp = 0; dp < 4; ++dp) {
                const int vc8 = 2 * dp + (lane >> 4);
                const uint32_t voff = (uint32_t)swb(vr, vc8);
                uint32_t vh4[4], vl4[4];
                ldsm_x4t(vh4[0], vh4[1], vh4[2], vh4[3], sb + SV0 + voff);
                ldsm_x4t(vl4[0], vl4[1], vl4[2], vl4[3], sb + SV1 + voff);
                mma_f16(Oa[2*dp],   AH, vh4[0], vh4[1]);
                mma_f16(Oa[2*dp],   AH, vl4[0], vl4[1]);
                mma_f16(Oa[2*dp],   AL, vh4[0], vh4[1]);
                mma_f16(Oa[2*dp+1], AH, vh4[2], vh4[3]);
                mma_f16(Oa[2*dp+1], AH, vl4[2], vl4[3]);
                mma_f16(Oa[2*dp+1], AL, vh4[2], vh4[3]);
            }
        }
    }

    // ---- epilogue ----
    const float iz0 = 1.0f / (Z0 * 0.9f);
    const float iz1 = 1.0f / (Z1 * 0.9f);
    float* orow0 = out + (((size_t)bh * S_ + rg0) << 6);
    float* orow1 = out + (((size_t)bh * S_ + rg1) << 6);
    #pragma unroll
    for (int dt = 0; dt < 8; ++dt) {
        float2 w0 = make_float2(Oa[dt][0] * iz0, Oa[dt][1] * iz0);
        float2 w1 = make_float2(Oa[dt][2] * iz1, Oa[dt][3] * iz1);
        *(float2*)(orow0 + dt * 8 + qc) = w0;
        *(float2*)(orow1 + dt * 8 + qc) = w1;
    }
}

// ---------------------------------------------------------------------------
extern "C" void kernel_launch(void* const* d_in, const int* in_sizes, int n_in,
                              void* d_out, int out_size)
{
    const float* query     = (const float*)d_in[0];
    const float* key       = (const float*)d_in[1];
    const float* value     = (const float*)d_in[2];
    const float* attn_mask = (const float*)d_in[3];
    const float* inv_scale = (const float*)d_in[4];
    const float* Wq = (const float*)d_in[5];
    const float* bq = (const float*)d_in[6];
    const float* Wk = (const float*)d_in[7];
    const float* bk = (const float*)d_in[8];
    const float* Wv = (const float*)d_in[9];
    const float* bv = (const float*)d_in[10];
    float* out = (float*)d_out;

    const int nblk = NTOK / 64;
    proj_kernel<<<nblk, 256>>>(query, Wq, bq, 0);
    proj_kernel<<<nblk, 256>>>(key,   Wk, bk, 1);
    proj_kernel<<<nblk, 256>>>(value, Wv, bv, 2);

    cudaFuncSetAttribute(attn_kernel,
                         cudaFuncAttributeMaxDynamicSharedMemorySize, SMEM_TOT);
    dim3 grid(S_ / BM, H_, B_);
    attn_kernel<<<grid, 256, SMEM_TOT>>>(attn_mask, inv_scale, out);
}

// round 11
// speedup vs baseline: 2.5052x; 1.0864x over previous
#include <cuda_runtime.h>
#include <cuda_fp16.h>
#include <cstdint>
#include <math.h>

#define B_ 2
#define H_ 16
#define S_ 2048
#define E_ 64
#define NTOK (B_*S_*H_)
#define BM 128
#define BN 64
#define NT_ (S_/BN)

// fp16 split levels of projected Q,K,V in [B,H,S,E] layout
__device__ __half g_q0[B_*H_*S_*E_];
__device__ __half g_q1[B_*H_*S_*E_];
__device__ __half g_k0[B_*H_*S_*E_];
__device__ __half g_k1[B_*H_*S_*E_];
__device__ __half g_v0[B_*H_*S_*E_];
__device__ __half g_v1[B_*H_*S_*E_];

// ---------------- helpers ----------------
__device__ __forceinline__ uint32_t smem_u32(const void* p) {
    uint32_t a;
    asm("{ .reg .u64 t; cvta.to.shared.u64 t, %1; cvt.u32.u64 %0, t; }" : "=r"(a) : "l"(p));
    return a;
}
__device__ __forceinline__ void cpasync16(uint32_t dst, const void* src) {
    asm volatile("cp.async.cg.shared.global [%0], [%1], 16;" :: "r"(dst), "l"(src));
}
#define CP_COMMIT() asm volatile("cp.async.commit_group;" ::: "memory")
#define CP_WAIT1()  asm volatile("cp.async.wait_group 1;" ::: "memory")
#define CP_WAIT0()  asm volatile("cp.async.wait_group 0;" ::: "memory")

__device__ __forceinline__ void ldsm_x4(uint32_t& r0, uint32_t& r1, uint32_t& r2,
                                        uint32_t& r3, uint32_t a) {
    asm volatile("ldmatrix.sync.aligned.m8n8.x4.shared.b16 {%0,%1,%2,%3}, [%4];"
                 : "=r"(r0), "=r"(r1), "=r"(r2), "=r"(r3) : "r"(a));
}
__device__ __forceinline__ void ldsm_x4t(uint32_t& r0, uint32_t& r1, uint32_t& r2,
                                         uint32_t& r3, uint32_t a) {
    asm volatile("ldmatrix.sync.aligned.m8n8.x4.trans.shared.b16 {%0,%1,%2,%3}, [%4];"
                 : "=r"(r0), "=r"(r1), "=r"(r2), "=r"(r3) : "r"(a));
}
__device__ __forceinline__ void mma_f16(float* c, const uint32_t* a,
                                        uint32_t b0, uint32_t b1) {
    asm volatile("mma.sync.aligned.m16n8k16.row.col.f32.f16.f16.f32 "
                 "{%0,%1,%2,%3}, {%4,%5,%6,%7}, {%8,%9}, {%0,%1,%2,%3};"
                 : "+f"(c[0]), "+f"(c[1]), "+f"(c[2]), "+f"(c[3])
                 : "r"(a[0]), "r"(a[1]), "r"(a[2]), "r"(a[3]), "r"(b0), "r"(b1));
}
__device__ __forceinline__ uint32_t packh2(float x, float y) {
    __half2 t = __floats2half2_rn(x, y);
    return *(uint32_t*)&t;
}

// ---------------- exact JAX threefry, key=(0,42), partitionable ----------------
__device__ __forceinline__ uint32_t threefry_bits_42(uint32_t c1) {
    const uint32_t ks1 = 42u, ks2 = 0x1BD11BDAu ^ 42u;
    uint32_t x0 = 0u, x1 = c1 + ks1;
#define TF_R(r) { x0 += x1; x1 = __funnelshift_l(x1, x1, (r)); x1 ^= x0; }
    TF_R(13) TF_R(15) TF_R(26) TF_R(6)
    x0 += ks1; x1 += ks2 + 1u;
    TF_R(17) TF_R(29) TF_R(16) TF_R(24)
    x0 += ks2; x1 += 2u;
    TF_R(13) TF_R(15) TF_R(26) TF_R(6)
    x1 += ks1 + 3u;
    TF_R(17) TF_R(29) TF_R(16) TF_R(24)
    x0 += ks1; x1 += ks2 + 4u;
    TF_R(13) TF_R(15) TF_R(26) TF_R(6)
    x0 += ks2; x1 += 5u;
#undef TF_R
    return x0 ^ x1;
}
__device__ __forceinline__ float jax_uniform(uint32_t bits) {
    return __uint_as_float((bits >> 9) | 0x3f800000u) - 1.0f;
}

// ---------------- projection with fp16 2-level split outputs ----------------
__global__ __launch_bounds__(256) void proj_kernel(
    const float* __restrict__ x, const float* __restrict__ W,
    const float* __restrict__ bias, int which)
{
    __shared__ float Xs[64][65];
    __shared__ float Ws[64][65];
    __shared__ float bs[64];
    __half* o0 = (which == 0) ? g_q0 : (which == 1) ? g_k0 : g_v0;
    __half* o1 = (which == 0) ? g_q1 : (which == 1) ? g_k1 : g_v1;
    const int tid = threadIdx.x;
    const int n0  = blockIdx.x * 64;
    #pragma unroll
    for (int it = 0; it < 4; ++it) {
        int elem = tid * 4 + it * 1024;
        int r = elem >> 6, c = elem & 63;
        float4 w4 = *(const float4*)(W + elem);
        Ws[r][c] = w4.x; Ws[r][c+1] = w4.y; Ws[r][c+2] = w4.z; Ws[r][c+3] = w4.w;
        float4 x4 = *(const float4*)(x + (size_t)n0 * 64 + elem);
        Xs[r][c] = x4.x; Xs[r][c+1] = x4.y; Xs[r][c+2] = x4.z; Xs[r][c+3] = x4.w;
    }
    if (tid < 64) bs[tid] = bias[tid];
    __syncthreads();
    const int tx = tid & 15, ty = tid >> 4;
    float acc[4][4] = {};
    #pragma unroll 8
    for (int d = 0; d < 64; ++d) {
        float a[4], b[4];
        #pragma unroll
        for (int i = 0; i < 4; ++i) a[i] = Xs[ty*4+i][d];
        #pragma unroll
        for (int j = 0; j < 4; ++j) b[j] = Ws[tx*4+j][d];
        #pragma unroll
        for (int i = 0; i < 4; ++i)
            #pragma unroll
            for (int j = 0; j < 4; ++j)
                acc[i][j] = fmaf(a[i], b[j], acc[i][j]);
    }
    #pragma unroll
    for (int i = 0; i < 4; ++i) {
        int n = n0 + ty*4 + i;
        int b_ = n >> 15, rem = n & 32767, s = rem >> 4, h = n & 15;
        size_t off = ((((size_t)b_ * H_ + h) * S_ + s) << 6);
        #pragma unroll
        for (int j = 0; j < 4; ++j) {
            int e = tx*4 + j;
            float v = acc[i][j] + bs[e];
            __half h0 = __float2half_rn(v);
            o0[off + e] = h0;
            o1[off + e] = __float2half_rn(v - __half2float(h0));
        }
    }
}

// ---------------- mma.sync fp16 flash attention, cp.async pipelined ----------------
// smem: Q (2 levels, 32KB) + double-buffered K0/K1/V0/V1 (2 x 32KB) = 96KB
#define SQ0 0
#define SQ1 16384
#define SKV 32768
#define KVB 32768              // bytes per KV buffer
#define SMEM_TOT 98304
__device__ __forceinline__ int swb(int r, int c8) {
    return r * 128 + ((c8 ^ (r & 7)) << 4);
}

__global__ __launch_bounds__(256, 2) void attn_kernel(
    const float* __restrict__ mask,
    const float* __restrict__ inv_scale,
    float* __restrict__ out)
{
    extern __shared__ char smem[];
    const uint32_t sb = smem_u32(smem);
    const int tid = threadIdx.x, warp = tid >> 5, lane = tid & 31;
    const int s0 = blockIdx.x * BM, h = blockIdx.y, b = blockIdx.z;
    const int bh = b * H_ + h;
    const float rscale = 1.0f / inv_scale[0];
    const size_t kplane = (size_t)bh * S_;

    // prologue: stage Q (2 levels) + KV tile 0 via cp.async, one group
    const size_t qrow = (size_t)bh * S_ + s0;
    for (int c = tid; c < 128 * 8; c += 256) {
        int r = c >> 3, c8 = c & 7;
        size_t ge = ((qrow + r) << 6) + (c8 << 3);
        int so = swb(r, c8);
        cpasync16(sb + SQ0 + so, g_q0 + ge);
        cpasync16(sb + SQ1 + so, g_q1 + ge);
    }
    for (int c = tid; c < 64 * 8; c += 256) {
        int r = c >> 3, c8 = c & 7;
        size_t ge = ((kplane + r) << 6) + (c8 << 3);
        int so = swb(r, c8);
        cpasync16(sb + SKV + 0     + so, g_k0 + ge);
        cpasync16(sb + SKV + 8192  + so, g_k1 + ge);
        cpasync16(sb + SKV + 16384 + so, g_v0 + ge);
        cpasync16(sb + SKV + 24576 + so, g_v1 + ge);
    }
    CP_COMMIT();

    const int qr = lane >> 2;
    const int qc = (lane & 3) << 1;
    const int rg0 = s0 + warp * 16 + qr;
    const int rg1 = rg0 + 8;
    const float* mrow0 = mask + ((size_t)b * S_ + rg0) * S_;
    const float* mrow1 = mask + ((size_t)b * S_ + rg1) * S_;
    const uint32_t cb0 = ((uint32_t)bh * S_ + (uint32_t)rg0) * S_;
    const uint32_t cb1 = ((uint32_t)bh * S_ + (uint32_t)rg1) * S_;

    float m0 = -INFINITY, m1 = -INFINITY, Z0 = 0.0f, Z1 = 0.0f;
    float Oa[8][4];
    #pragma unroll
    for (int d = 0; d < 8; ++d)
        #pragma unroll
        for (int j = 0; j < 4; ++j) Oa[d][j] = 0.0f;

    for (int it = 0; it < NT_; ++it) {
        const int t0 = it * BN;
        // prefetch next KV tile into the other buffer
        if (it + 1 < NT_) {
            const uint32_t nb = sb + SKV + (uint32_t)(((it + 1) & 1) * KVB);
            const size_t koff = kplane + (size_t)(t0 + BN);
            for (int c = tid; c < 64 * 8; c += 256) {
                int r = c >> 3, c8 = c & 7;
                size_t ge = ((koff + r) << 6) + (c8 << 3);
                int so = swb(r, c8);
                cpasync16(nb + 0     + so, g_k0 + ge);
                cpasync16(nb + 8192  + so, g_k1 + ge);
                cpasync16(nb + 16384 + so, g_v0 + ge);
                cpasync16(nb + 24576 + so, g_v1 + ge);
            }
            CP_COMMIT();
            CP_WAIT1();
        } else {
            CP_WAIT0();
        }
        __syncthreads();
        const uint32_t kb = sb + SKV + (uint32_t)((it & 1) * KVB);

        // ---- QK^T: fp16 2-level, 3 terms (hh, hm, mh) ----
        float sacc[8][4];
        #pragma unroll
        for (int nt = 0; nt < 8; ++nt)
            #pragma unroll
            for (int j = 0; j < 4; ++j) sacc[nt][j] = 0.0f;

        #pragma unroll
        for (int ks = 0; ks < 4; ++ks) {
            const int lr  = warp * 16 + (lane & 7) + ((lane >> 3) & 1) * 8;
            const int lc8 = 2 * ks + (lane >> 4);
            const uint32_t aoff = (uint32_t)swb(lr, lc8);
            uint32_t aH[4], aM[4];
            ldsm_x4(aH[0], aH[1], aH[2], aH[3], sb + SQ0 + aoff);
            ldsm_x4(aM[0], aM[1], aM[2], aM[3], sb + SQ1 + aoff);
            const int br  = (lane & 7) + ((lane >> 4) << 3);
            const int bc8 = 2 * ks + ((lane >> 3) & 1);
            #pragma unroll
            for (int np = 0; np < 4; ++np) {
                const uint32_t boff = (uint32_t)swb(np * 16 + br, bc8);
                uint32_t bh4[4], bm4[4];
                ldsm_x4(bh4[0], bh4[1], bh4[2], bh4[3], kb + boff);
                ldsm_x4(bm4[0], bm4[1], bm4[2], bm4[3], kb + 8192 + boff);
                mma_f16(sacc[2*np],   aH, bh4[0], bh4[1]);
                mma_f16(sacc[2*np],   aH, bm4[0], bm4[1]);
                mma_f16(sacc[2*np],   aM, bh4[0], bh4[1]);
                mma_f16(sacc[2*np+1], aH, bh4[2], bh4[3]);
                mma_f16(sacc[2*np+1], aH, bm4[2], bm4[3]);
                mma_f16(sacc[2*np+1], aM, bh4[2], bh4[3]);
            }
        }

        // ---- scale + mask (direct LDG), tile row max ----
        float tm0 = -INFINITY, tm1 = -INFINITY;
        #pragma unroll
        for (int nt = 0; nt < 8; ++nt) {
            float2 mk0 = *(const float2*)(mrow0 + t0 + nt * 8 + qc);
            float2 mk1 = *(const float2*)(mrow1 + t0 + nt * 8 + qc);
            sacc[nt][0] = fmaf(sacc[nt][0], rscale, mk0.x);
            sacc[nt][1] = fmaf(sacc[nt][1], rscale, mk0.y);
            sacc[nt][2] = fmaf(sacc[nt][2], rscale, mk1.x);
            sacc[nt][3] = fmaf(sacc[nt][3], rscale, mk1.y);
            tm0 = fmaxf(tm0, fmaxf(sacc[nt][0], sacc[nt][1]));
            tm1 = fmaxf(tm1, fmaxf(sacc[nt][2], sacc[nt][3]));
        }
        tm0 = fmaxf(tm0, __shfl_xor_sync(0xffffffffu, tm0, 1));
        tm0 = fmaxf(tm0, __shfl_xor_sync(0xffffffffu, tm0, 2));
        tm1 = fmaxf(tm1, __shfl_xor_sync(0xffffffffu, tm1, 1));
        tm1 = fmaxf(tm1, __shfl_xor_sync(0xffffffffu, tm1, 2));
        const float mn0 = fmaxf(m0, tm0), mn1 = fmaxf(m1, tm1);
        const float f0 = __expf(m0 - mn0), f1 = __expf(m1 - mn1);
        m0 = mn0; m1 = mn1;

        // ---- exp + gated exact dropout ----
        float zs0 = 0.0f, zs1 = 0.0f;
        #pragma unroll
        for (int nt = 0; nt < 8; ++nt) {
            const uint32_t colb = (uint32_t)(t0 + nt * 8 + qc);
            #pragma unroll
            for (int j = 0; j < 2; ++j) {
                float p = __expf(sacc[nt][j] - mn0);
                zs0 += p;
                if (p >= 1e-10f) {
                    uint32_t bits = threefry_bits_42(cb0 + colb + (uint32_t)j);
                    if (!(jax_uniform(bits) < 0.9f)) p = 0.0f;
                }
                sacc[nt][j] = p;
            }
            #pragma unroll
            for (int j = 0; j < 2; ++j) {
                float p = __expf(sacc[nt][2 + j] - mn1);
                zs1 += p;
                if (p >= 1e-10f) {
                    uint32_t bits = threefry_bits_42(cb1 + colb + (uint32_t)j);
                    if (!(jax_uniform(bits) < 0.9f)) p = 0.0f;
                }
                sacc[nt][2 + j] = p;
            }
        }
        zs0 += __shfl_xor_sync(0xffffffffu, zs0, 1);
        zs0 += __shfl_xor_sync(0xffffffffu, zs0, 2);
        zs1 += __shfl_xor_sync(0xffffffffu, zs1, 1);
        zs1 += __shfl_xor_sync(0xffffffffu, zs1, 2);
        Z0 = Z0 * f0 + zs0;
        Z1 = Z1 * f1 + zs1;

        // ---- rescale O ----
        #pragma unroll
        for (int d = 0; d < 8; ++d) {
            Oa[d][0] *= f0; Oa[d][1] *= f0;
            Oa[d][2] *= f1; Oa[d][3] *= f1;
        }

        // ---- PV: fp16 2-level P from regs, V x4t from smem ----
        #pragma unroll
        for (int ks = 0; ks < 4; ++ks) {
            uint32_t AH[4], AL[4];
            #pragma unroll
            for (int half = 0; half < 2; ++half) {
                const int nt = 2 * ks + half;
                float pA = sacc[nt][0], pB = sacc[nt][1];
                float pC = sacc[nt][2], pD = sacc[nt][3];
                __half2 hAB = __floats2half2_rn(pA, pB);
                __half2 hCD = __floats2half2_rn(pC, pD);
                AH[half * 2 + 0] = *(uint32_t*)&hAB;
                AH[half * 2 + 1] = *(uint32_t*)&hCD;
                float lA = pA - __half2float(__low2half(hAB));
                float lB = pB - __half2float(__high2half(hAB));
                float lC = pC - __half2float(__low2half(hCD));
                float lD = pD - __half2float(__high2half(hCD));
                AL[half * 2 + 0] = packh2(lA, lB);
                AL[half * 2 + 1] = packh2(lC, lD);
            }
            const int vr = 16 * ks + (lane & 15);
            #pragma unroll
            for (int dp = 0; dp < 4; ++dp) {
                const int vc8 = 2 * dp + (lane >> 4);
                const uint32_t voff = (uint32_t)swb(vr, vc8);
                uint32_t vh4[4], vl4[4];
                ldsm_x4t(vh4[0], vh4[1], vh4[2], vh4[3], kb + 16384 + voff);
                ldsm_x4t(vl4[0], vl4[1], vl4[2], vl4[3], kb + 24576 + voff);
                mma_f16(Oa[2*dp],   AH, vh4[0], vh4[1]);
                mma_f16(Oa[2*dp],   AH, vl4[0], vl4[1]);
                mma_f16(Oa[2*dp],   AL, vh4[0], vh4[1]);
                mma_f16(Oa[2*dp+1], AH, vh4[2], vh4[3]);
                mma_f16(Oa[2*dp+1], AH, vl4[2], vl4[3]);
                mma_f16(Oa[2*dp+1], AL, vh4[2], vh4[3]);
            }
        }
        __syncthreads();
    }

    // ---- epilogue ----
    const float iz0 = 1.0f / (Z0 * 0.9f);
    const float iz1 = 1.0f / (Z1 * 0.9f);
    float* orow0 = out + (((size_t)bh * S_ + rg0) << 6);
    float* orow1 = out + (((size_t)bh * S_ + rg1) << 6);
    #pragma unroll
    for (int dt = 0; dt < 8; ++dt) {
        float2 w0 = make_float2(Oa[dt][0] * iz0, Oa[dt][1] * iz0);
        float2 w1 = make_float2(Oa[dt][2] * iz1, Oa[dt][3] * iz1);
        *(float2*)(orow0 + dt * 8 + qc) = w0;
        *(float2*)(orow1 + dt * 8 + qc) = w1;
    }
}

// ---------------------------------------------------------------------------
extern "C" void kernel_launch(void* const* d_in, const int* in_sizes, int n_in,
                              void* d_out, int out_size)
{
    const float* query     = (const float*)d_in[0];
    const float* key       = (const float*)d_in[1];
    const float* value     = (const float*)d_in[2];
    const float* attn_mask = (const float*)d_in[3];
    const float* inv_scale = (const float*)d_in[4];
    const float* Wq = (const float*)d_in[5];
    const float* bq = (const float*)d_in[6];
    const float* Wk = (const float*)d_in[7];
    const float* bk = (const float*)d_in[8];
    const float* Wv = (const float*)d_in[9];
    const float* bv = (const float*)d_in[10];
    float* out = (float*)d_out;

    const int nblk = NTOK / 64;
    proj_kernel<<<nblk, 256>>>(query, Wq, bq, 0);
    proj_kernel<<<nblk, 256>>>(key,   Wk, bk, 1);
    proj_kernel<<<nblk, 256>>>(value, Wv, bv, 2);

    cudaFuncSetAttribute(attn_kernel,
                         cudaFuncAttributeMaxDynamicSharedMemorySize, SMEM_TOT);
    dim3 grid(S_ / BM, H_, B_);
    attn_kernel<<<grid, 256, SMEM_TOT>>>(attn_mask, inv_scale, out);
}

// round 12
// speedup vs baseline: 2.5531x; 1.0192x over previous
#include <cuda_runtime.h>
#include <cuda_fp16.h>
#include <cstdint>
#include <math.h>

#define B_ 2
#define H_ 16
#define S_ 2048
#define E_ 64
#define NTOK (B_*S_*H_)
#define BM 128
#define BN 64
#define NT_ (S_/BN)

// fp16 split levels of projected Q,K,V in [B,H,S,E] layout
__device__ __half g_q0[B_*H_*S_*E_];
__device__ __half g_q1[B_*H_*S_*E_];
__device__ __half g_k0[B_*H_*S_*E_];
__device__ __half g_k1[B_*H_*S_*E_];
__device__ __half g_v0[B_*H_*S_*E_];
__device__ __half g_v1[B_*H_*S_*E_];

// ---------------- helpers ----------------
__device__ __forceinline__ uint32_t smem_u32(const void* p) {
    uint32_t a;
    asm("{ .reg .u64 t; cvta.to.shared.u64 t, %1; cvt.u32.u64 %0, t; }" : "=r"(a) : "l"(p));
    return a;
}
__device__ __forceinline__ void cpasync16(uint32_t dst, const void* src) {
    asm volatile("cp.async.cg.shared.global [%0], [%1], 16;" :: "r"(dst), "l"(src));
}
#define CP_COMMIT() asm volatile("cp.async.commit_group;" ::: "memory")
#define CP_WAIT1()  asm volatile("cp.async.wait_group 1;" ::: "memory")
#define CP_WAIT0()  asm volatile("cp.async.wait_group 0;" ::: "memory")

__device__ __forceinline__ void ldsm_x4(uint32_t& r0, uint32_t& r1, uint32_t& r2,
                                        uint32_t& r3, uint32_t a) {
    asm volatile("ldmatrix.sync.aligned.m8n8.x4.shared.b16 {%0,%1,%2,%3}, [%4];"
                 : "=r"(r0), "=r"(r1), "=r"(r2), "=r"(r3) : "r"(a));
}
__device__ __forceinline__ void ldsm_x4t(uint32_t& r0, uint32_t& r1, uint32_t& r2,
                                         uint32_t& r3, uint32_t a) {
    asm volatile("ldmatrix.sync.aligned.m8n8.x4.trans.shared.b16 {%0,%1,%2,%3}, [%4];"
                 : "=r"(r0), "=r"(r1), "=r"(r2), "=r"(r3) : "r"(a));
}
__device__ __forceinline__ void mma_f16(float* c, const uint32_t* a,
                                        uint32_t b0, uint32_t b1) {
    asm volatile("mma.sync.aligned.m16n8k16.row.col.f32.f16.f16.f32 "
                 "{%0,%1,%2,%3}, {%4,%5,%6,%7}, {%8,%9}, {%0,%1,%2,%3};"
                 : "+f"(c[0]), "+f"(c[1]), "+f"(c[2]), "+f"(c[3])
                 : "r"(a[0]), "r"(a[1]), "r"(a[2]), "r"(a[3]), "r"(b0), "r"(b1));
}
__device__ __forceinline__ uint32_t packh2(float x, float y) {
    __half2 t = __floats2half2_rn(x, y);
    return *(uint32_t*)&t;
}

// ---------------- exact JAX threefry, key=(0,42), partitionable ----------------
__device__ __forceinline__ uint32_t threefry_bits_42(uint32_t c1) {
    const uint32_t ks1 = 42u, ks2 = 0x1BD11BDAu ^ 42u;
    uint32_t x0 = 0u, x1 = c1 + ks1;
#define TF_R(r) { x0 += x1; x1 = __funnelshift_l(x1, x1, (r)); x1 ^= x0; }
    TF_R(13) TF_R(15) TF_R(26) TF_R(6)
    x0 += ks1; x1 += ks2 + 1u;
    TF_R(17) TF_R(29) TF_R(16) TF_R(24)
    x0 += ks2; x1 += 2u;
    TF_R(13) TF_R(15) TF_R(26) TF_R(6)
    x1 += ks1 + 3u;
    TF_R(17) TF_R(29) TF_R(16) TF_R(24)
    x0 += ks1; x1 += ks2 + 4u;
    TF_R(13) TF_R(15) TF_R(26) TF_R(6)
    x0 += ks2; x1 += 5u;
#undef TF_R
    return x0 ^ x1;
}
__device__ __forceinline__ float jax_uniform(uint32_t bits) {
    return __uint_as_float((bits >> 9) | 0x3f800000u) - 1.0f;
}

// ---------------- projection with fp16 2-level split outputs ----------------
__global__ __launch_bounds__(256) void proj_kernel(
    const float* __restrict__ x, const float* __restrict__ W,
    const float* __restrict__ bias, int which)
{
    __shared__ float Xs[64][65];
    __shared__ float Ws[64][65];
    __shared__ float bs[64];
    __half* o0 = (which == 0) ? g_q0 : (which == 1) ? g_k0 : g_v0;
    __half* o1 = (which == 0) ? g_q1 : (which == 1) ? g_k1 : g_v1;
    const int tid = threadIdx.x;
    const int n0  = blockIdx.x * 64;
    #pragma unroll
    for (int it = 0; it < 4; ++it) {
        int elem = tid * 4 + it * 1024;
        int r = elem >> 6, c = elem & 63;
        float4 w4 = *(const float4*)(W + elem);
        Ws[r][c] = w4.x; Ws[r][c+1] = w4.y; Ws[r][c+2] = w4.z; Ws[r][c+3] = w4.w;
        float4 x4 = *(const float4*)(x + (size_t)n0 * 64 + elem);
        Xs[r][c] = x4.x; Xs[r][c+1] = x4.y; Xs[r][c+2] = x4.z; Xs[r][c+3] = x4.w;
    }
    if (tid < 64) bs[tid] = bias[tid];
    __syncthreads();
    const int tx = tid & 15, ty = tid >> 4;
    float acc[4][4] = {};
    #pragma unroll 8
    for (int d = 0; d < 64; ++d) {
        float a[4], b[4];
        #pragma unroll
        for (int i = 0; i < 4; ++i) a[i] = Xs[ty*4+i][d];
        #pragma unroll
        for (int j = 0; j < 4; ++j) b[j] = Ws[tx*4+j][d];
        #pragma unroll
        for (int i = 0; i < 4; ++i)
            #pragma unroll
            for (int j = 0; j < 4; ++j)
                acc[i][j] = fmaf(a[i], b[j], acc[i][j]);
    }
    #pragma unroll
    for (int i = 0; i < 4; ++i) {
        int n = n0 + ty*4 + i;
        int b_ = n >> 15, rem = n & 32767, s = rem >> 4, h = n & 15;
        size_t off = ((((size_t)b_ * H_ + h) * S_ + s) << 6);
        #pragma unroll
        for (int j = 0; j < 4; ++j) {
            int e = tx*4 + j;
            float v = acc[i][j] + bs[e];
            __half h0 = __float2half_rn(v);
            o0[off + e] = h0;
            o1[off + e] = __float2half_rn(v - __half2float(h0));
        }
    }
}

// ---------------- mma.sync fp16 flash attention, cp.async + PV sparsity ----------------
#define SQ0 0
#define SQ1 16384
#define SKV 32768
#define KVB 32768
#define SMEM_TOT 98304
__device__ __forceinline__ int swb(int r, int c8) {
    return r * 128 + ((c8 ^ (r & 7)) << 4);
}

__global__ __launch_bounds__(256, 2) void attn_kernel(
    const float* __restrict__ mask,
    const float* __restrict__ inv_scale,
    float* __restrict__ out)
{
    extern __shared__ char smem[];
    const uint32_t sb = smem_u32(smem);
    const int tid = threadIdx.x, warp = tid >> 5, lane = tid & 31;
    const int s0 = blockIdx.x * BM, h = blockIdx.y, b = blockIdx.z;
    const int bh = b * H_ + h;
    const float rscale = 1.0f / inv_scale[0];
    const size_t kplane = (size_t)bh * S_;

    // prologue: stage Q (2 levels) + KV tile 0 via cp.async
    const size_t qrow = (size_t)bh * S_ + s0;
    for (int c = tid; c < 128 * 8; c += 256) {
        int r = c >> 3, c8 = c & 7;
        size_t ge = ((qrow + r) << 6) + (c8 << 3);
        int so = swb(r, c8);
        cpasync16(sb + SQ0 + so, g_q0 + ge);
        cpasync16(sb + SQ1 + so, g_q1 + ge);
    }
    for (int c = tid; c < 64 * 8; c += 256) {
        int r = c >> 3, c8 = c & 7;
        size_t ge = ((kplane + r) << 6) + (c8 << 3);
        int so = swb(r, c8);
        cpasync16(sb + SKV + 0     + so, g_k0 + ge);
        cpasync16(sb + SKV + 8192  + so, g_k1 + ge);
        cpasync16(sb + SKV + 16384 + so, g_v0 + ge);
        cpasync16(sb + SKV + 24576 + so, g_v1 + ge);
    }
    CP_COMMIT();

    const int qr = lane >> 2;
    const int qc = (lane & 3) << 1;
    const int rg0 = s0 + warp * 16 + qr;
    const int rg1 = rg0 + 8;
    const float* mrow0 = mask + ((size_t)b * S_ + rg0) * S_;
    const float* mrow1 = mask + ((size_t)b * S_ + rg1) * S_;
    const uint32_t cb0 = ((uint32_t)bh * S_ + (uint32_t)rg0) * S_;
    const uint32_t cb1 = ((uint32_t)bh * S_ + (uint32_t)rg1) * S_;

    float m0 = -INFINITY, m1 = -INFINITY, Z0 = 0.0f, Z1 = 0.0f;
    float Oa[8][4];
    #pragma unroll
    for (int d = 0; d < 8; ++d)
        #pragma unroll
        for (int j = 0; j < 4; ++j) Oa[d][j] = 0.0f;

    for (int it = 0; it < NT_; ++it) {
        const int t0 = it * BN;
        if (it + 1 < NT_) {
            const uint32_t nb = sb + SKV + (uint32_t)(((it + 1) & 1) * KVB);
            const size_t koff = kplane + (size_t)(t0 + BN);
            for (int c = tid; c < 64 * 8; c += 256) {
                int r = c >> 3, c8 = c & 7;
                size_t ge = ((koff + r) << 6) + (c8 << 3);
                int so = swb(r, c8);
                cpasync16(nb + 0     + so, g_k0 + ge);
                cpasync16(nb + 8192  + so, g_k1 + ge);
                cpasync16(nb + 16384 + so, g_v0 + ge);
                cpasync16(nb + 24576 + so, g_v1 + ge);
            }
            CP_COMMIT();
            CP_WAIT1();
        } else {
            CP_WAIT0();
        }
        __syncthreads();
        const uint32_t kb = sb + SKV + (uint32_t)((it & 1) * KVB);

        // ---- QK^T: fp16 2-level, 3 terms ----
        float sacc[8][4];
        #pragma unroll
        for (int nt = 0; nt < 8; ++nt)
            #pragma unroll
            for (int j = 0; j < 4; ++j) sacc[nt][j] = 0.0f;

        #pragma unroll
        for (int ks = 0; ks < 4; ++ks) {
            const int lr  = warp * 16 + (lane & 7) + ((lane >> 3) & 1) * 8;
            const int lc8 = 2 * ks + (lane >> 4);
            const uint32_t aoff = (uint32_t)swb(lr, lc8);
            uint32_t aH[4], aM[4];
            ldsm_x4(aH[0], aH[1], aH[2], aH[3], sb + SQ0 + aoff);
            ldsm_x4(aM[0], aM[1], aM[2], aM[3], sb + SQ1 + aoff);
            const int br  = (lane & 7) + ((lane >> 4) << 3);
            const int bc8 = 2 * ks + ((lane >> 3) & 1);
            #pragma unroll
            for (int np = 0; np < 4; ++np) {
                const uint32_t boff = (uint32_t)swb(np * 16 + br, bc8);
                uint32_t bh4[4], bm4[4];
                ldsm_x4(bh4[0], bh4[1], bh4[2], bh4[3], kb + boff);
                ldsm_x4(bm4[0], bm4[1], bm4[2], bm4[3], kb + 8192 + boff);
                mma_f16(sacc[2*np],   aH, bh4[0], bh4[1]);
                mma_f16(sacc[2*np],   aH, bm4[0], bm4[1]);
                mma_f16(sacc[2*np],   aM, bh4[0], bh4[1]);
                mma_f16(sacc[2*np+1], aH, bh4[2], bh4[3]);
                mma_f16(sacc[2*np+1], aH, bm4[2], bm4[3]);
                mma_f16(sacc[2*np+1], aM, bh4[2], bh4[3]);
            }
        }

        // ---- scale + mask (direct LDG), tile row max ----
        float tm0 = -INFINITY, tm1 = -INFINITY;
        #pragma unroll
        for (int nt = 0; nt < 8; ++nt) {
            float2 mk0 = *(const float2*)(mrow0 + t0 + nt * 8 + qc);
            float2 mk1 = *(const float2*)(mrow1 + t0 + nt * 8 + qc);
            sacc[nt][0] = fmaf(sacc[nt][0], rscale, mk0.x);
            sacc[nt][1] = fmaf(sacc[nt][1], rscale, mk0.y);
            sacc[nt][2] = fmaf(sacc[nt][2], rscale, mk1.x);
            sacc[nt][3] = fmaf(sacc[nt][3], rscale, mk1.y);
            tm0 = fmaxf(tm0, fmaxf(sacc[nt][0], sacc[nt][1]));
            tm1 = fmaxf(tm1, fmaxf(sacc[nt][2], sacc[nt][3]));
        }
        tm0 = fmaxf(tm0, __shfl_xor_sync(0xffffffffu, tm0, 1));
        tm0 = fmaxf(tm0, __shfl_xor_sync(0xffffffffu, tm0, 2));
        tm1 = fmaxf(tm1, __shfl_xor_sync(0xffffffffu, tm1, 1));
        tm1 = fmaxf(tm1, __shfl_xor_sync(0xffffffffu, tm1, 2));
        const float mn0 = fmaxf(m0, tm0), mn1 = fmaxf(m1, tm1);
        const float f0 = __expf(m0 - mn0), f1 = __expf(m1 - mn1);
        m0 = mn0; m1 = mn1;

        // ---- exp + gated exact dropout ----
        float zs0 = 0.0f, zs1 = 0.0f;
        #pragma unroll
        for (int nt = 0; nt < 8; ++nt) {
            const uint32_t colb = (uint32_t)(t0 + nt * 8 + qc);
            #pragma unroll
            for (int j = 0; j < 2; ++j) {
                float p = __expf(sacc[nt][j] - mn0);
                zs0 += p;
                if (p >= 1e-10f) {
                    uint32_t bits = threefry_bits_42(cb0 + colb + (uint32_t)j);
                    if (!(jax_uniform(bits) < 0.9f)) p = 0.0f;
                }
                sacc[nt][j] = p;
            }
            #pragma unroll
            for (int j = 0; j < 2; ++j) {
                float p = __expf(sacc[nt][2 + j] - mn1);
                zs1 += p;
                if (p >= 1e-10f) {
                    uint32_t bits = threefry_bits_42(cb1 + colb + (uint32_t)j);
                    if (!(jax_uniform(bits) < 0.9f)) p = 0.0f;
                }
                sacc[nt][2 + j] = p;
            }
        }
        zs0 += __shfl_xor_sync(0xffffffffu, zs0, 1);
        zs0 += __shfl_xor_sync(0xffffffffu, zs0, 2);
        zs1 += __shfl_xor_sync(0xffffffffu, zs1, 1);
        zs1 += __shfl_xor_sync(0xffffffffu, zs1, 2);
        Z0 = Z0 * f0 + zs0;
        Z1 = Z1 * f1 + zs1;

        // ---- rescale O (skip when f == 1 for both halves) ----
        if (f0 != 1.0f || f1 != 1.0f) {
            #pragma unroll
            for (int d = 0; d < 8; ++d) {
                Oa[d][0] *= f0; Oa[d][1] *= f0;
                Oa[d][2] *= f1; Oa[d][3] *= f1;
            }
        }

        // ---- PV with fragment-level sparsity skip ----
        #pragma unroll
        for (int ks = 0; ks < 4; ++ks) {
            // does any lane hold a significant p in key fragment 16ks..16ks+15?
            float pmax = fmaxf(
                fmaxf(fmaxf(sacc[2*ks][0], sacc[2*ks][1]),
                      fmaxf(sacc[2*ks][2], sacc[2*ks][3])),
                fmaxf(fmaxf(sacc[2*ks+1][0], sacc[2*ks+1][1]),
                      fmaxf(sacc[2*ks+1][2], sacc[2*ks+1][3])));
            if (!__ballot_sync(0xffffffffu, pmax >= 1e-10f)) continue;

            uint32_t AH[4], AL[4];
            #pragma unroll
            for (int half = 0; half < 2; ++half) {
                const int nt = 2 * ks + half;
                float pA = sacc[nt][0], pB = sacc[nt][1];
                float pC = sacc[nt][2], pD = sacc[nt][3];
                __half2 hAB = __floats2half2_rn(pA, pB);
                __half2 hCD = __floats2half2_rn(pC, pD);
                AH[half * 2 + 0] = *(uint32_t*)&hAB;
                AH[half * 2 + 1] = *(uint32_t*)&hCD;
                float lA = pA - __half2float(__low2half(hAB));
                float lB = pB - __half2float(__high2half(hAB));
                float lC = pC - __half2float(__low2half(hCD));
                float lD = pD - __half2float(__high2half(hCD));
                AL[half * 2 + 0] = packh2(lA, lB);
                AL[half * 2 + 1] = packh2(lC, lD);
            }
            const int vr = 16 * ks + (lane & 15);
            #pragma unroll
            for (int dp = 0; dp < 4; ++dp) {
                const int vc8 = 2 * dp + (lane >> 4);
                const uint32_t voff = (uint32_t)swb(vr, vc8);
                uint32_t vh4[4], vl4[4];
                ldsm_x4t(vh4[0], vh4[1], vh4[2], vh4[3], kb + 16384 + voff);
                ldsm_x4t(vl4[0], vl4[1], vl4[2], vl4[3], kb + 24576 + voff);
                mma_f16(Oa[2*dp],   AH, vh4[0], vh4[1]);
                mma_f16(Oa[2*dp],   AH, vl4[0], vl4[1]);
                mma_f16(Oa[2*dp],   AL, vh4[0], vh4[1]);
                mma_f16(Oa[2*dp+1], AH, vh4[2], vh4[3]);
                mma_f16(Oa[2*dp+1], AH, vl4[2], vl4[3]);
                mma_f16(Oa[2*dp+1], AL, vh4[2], vh4[3]);
            }
        }
        __syncthreads();
    }

    // ---- epilogue ----
    const float iz0 = 1.0f / (Z0 * 0.9f);
    const float iz1 = 1.0f / (Z1 * 0.9f);
    float* orow0 = out + (((size_t)bh * S_ + rg0) << 6);
    float* orow1 = out + (((size_t)bh * S_ + rg1) << 6);
    #pragma unroll
    for (int dt = 0; dt < 8; ++dt) {
        float2 w0 = make_float2(Oa[dt][0] * iz0, Oa[dt][1] * iz0);
        float2 w1 = make_float2(Oa[dt][2] * iz1, Oa[dt][3] * iz1);
        *(float2*)(orow0 + dt * 8 + qc) = w0;
        *(float2*)(orow1 + dt * 8 + qc) = w1;
    }
}

// ---------------------------------------------------------------------------
extern "C" void kernel_launch(void* const* d_in, const int* in_sizes, int n_in,
                              void* d_out, int out_size)
{
    const float* query     = (const float*)d_in[0];
    const float* key       = (const float*)d_in[1];
    const float* value     = (const float*)d_in[2];
    const float* attn_mask = (const float*)d_in[3];
    const float* inv_scale = (const float*)d_in[4];
    const float* Wq = (const float*)d_in[5];
    const float* bq = (const float*)d_in[6];
    const float* Wk = (const float*)d_in[7];
    const float* bk = (const float*)d_in[8];
    const float* Wv = (const float*)d_in[9];
    const float* bv = (const float*)d_in[10];
    float* out = (float*)d_out;

    const int nblk = NTOK / 64;
    proj_kernel<<<nblk, 256>>>(query, Wq, bq, 0);
    proj_kernel<<<nblk, 256>>>(key,   Wk, bk, 1);
    proj_kernel<<<nblk, 256>>>(value, Wv, bv, 2);

    cudaFuncSetAttribute(attn_kernel,
                         cudaFuncAttributeMaxDynamicSharedMemorySize, SMEM_TOT);
    dim3 grid(S_ / BM, H_, B_);
    attn_kernel<<<grid, 256, SMEM_TOT>>>(attn_mask, inv_scale, out);
}